// round 7
// baseline (speedup 1.0000x reference)
#include <cuda_runtime.h>
#include <cuda_bf16.h>
#include <cstdint>

#define BB 8192   // batch
#define DD 1024   // dim
#define KK 4096   // codebook size
#define LL 8      // max word length
#define KSPLIT 6144   // 6 * 1024 (bf16 split pairings along K)
#define MTOT (BB + KK) // 12288 unified GEMM rows

// ---------------- persistent scratch ----------------
__device__ float         g_scores[BB * KK];            // 134 MB
__device__ float         g_gram[KK * KK];              //  67 MB
__device__ float         g_norm2[BB];
__device__ float         g_idx_scratch[BB * LL];
__device__ __nv_bfloat16 g_TC[(size_t)MTOT * KSPLIT];  // [targets;codebook] A-variant (151 MB)
__device__ __nv_bfloat16 g_Cb[(size_t)KK * KSPLIT];    // codebook B-variant (50 MB)

__constant__ float c_decay[LL] = {
    1.0f, 0.9f, 0.81f, 0.729f, 0.6561f, 0.59049f, 0.531441f, 0.4782969f
};

// ---------------- split conversion ----------------
// A-variant slots: [hi, mid, lo, hi, hi, mid]; B-variant: [hi, hi, hi, mid, lo, mid]
// => pairings hh + mh + lh + hm + hl + mm (drops ml, lm, ll ~ 2^-27)
__global__ __launch_bounds__(256) void split_targets(const float* __restrict__ src) {
    int i = blockIdx.x * 256 + threadIdx.x;             // over BB*DD
    float a = src[i];
    __nv_bfloat16 hi = __float2bfloat16(a);
    float r1 = a - __bfloat162float(hi);
    __nv_bfloat16 mid = __float2bfloat16(r1);
    __nv_bfloat16 lo  = __float2bfloat16(r1 - __bfloat162float(mid));
    size_t base = (size_t)(i >> 10) * KSPLIT + (i & 1023);
    g_TC[base]        = hi;  g_TC[base + 1024] = mid; g_TC[base + 2048] = lo;
    g_TC[base + 3072] = hi;  g_TC[base + 4096] = hi;  g_TC[base + 5120] = mid;
}
__global__ __launch_bounds__(256) void split_codebook(const float* __restrict__ src) {
    int i = blockIdx.x * 256 + threadIdx.x;             // over KK*DD
    float a = src[i];
    __nv_bfloat16 hi = __float2bfloat16(a);
    float r1 = a - __bfloat162float(hi);
    __nv_bfloat16 mid = __float2bfloat16(r1);
    __nv_bfloat16 lo  = __float2bfloat16(r1 - __bfloat162float(mid));
    size_t basea = (size_t)(BB + (i >> 10)) * KSPLIT + (i & 1023);
    g_TC[basea]        = hi;  g_TC[basea + 1024] = mid; g_TC[basea + 2048] = lo;
    g_TC[basea + 3072] = hi;  g_TC[basea + 4096] = hi;  g_TC[basea + 5120] = mid;
    size_t baseb = (size_t)(i >> 10) * KSPLIT + (i & 1023);
    g_Cb[baseb]        = hi;  g_Cb[baseb + 1024] = hi;  g_Cb[baseb + 2048] = hi;
    g_Cb[baseb + 3072] = mid; g_Cb[baseb + 4096] = lo;  g_Cb[baseb + 5120] = mid;
}

// ---------------- unified mma.sync bf16 GEMM ----------------
// [scores; gram] = g_TC[12288,6144] @ g_Cb[4096,6144]^T
#define BMT 128
#define BN 128
#define BKT 64          // bf16 k per stage (4 x k16)
#define NSTG 3
#define NKT (KSPLIT / BKT)       // 96
#define ASTRIDE 144              // 128B data + 16B pad per smem row
#define B_OFF (BMT * ASTRIDE)    // 18432
#define STAGE_BYTES ((BMT + BN) * ASTRIDE)   // 36864

__device__ __forceinline__ uint32_t smem_u32(const void* p) {
    uint32_t a;
    asm("{ .reg .u64 t; cvta.to.shared.u64 t, %1; cvt.u32.u64 %0, t; }" : "=r"(a) : "l"(p));
    return a;
}
__device__ __forceinline__ void cp16(uint32_t dst, const void* src) {
    asm volatile("cp.async.cg.shared.global [%0], [%1], 16;" :: "r"(dst), "l"(src) : "memory");
}
#define CP_COMMIT() asm volatile("cp.async.commit_group;" ::: "memory")
#define CP_WAIT(n)  asm volatile("cp.async.wait_group %0;" :: "n"(n) : "memory")

__device__ __forceinline__ void ldsm4(uint32_t& r0, uint32_t& r1, uint32_t& r2, uint32_t& r3,
                                      uint32_t addr) {
    asm volatile("ldmatrix.sync.aligned.m8n8.x4.shared.b16 {%0,%1,%2,%3}, [%4];"
                 : "=r"(r0), "=r"(r1), "=r"(r2), "=r"(r3) : "r"(addr));
}
__device__ __forceinline__ void mma16816(float* c, const uint32_t* a, const uint32_t* b) {
    asm volatile(
        "mma.sync.aligned.m16n8k16.row.col.f32.bf16.bf16.f32 "
        "{%0,%1,%2,%3}, {%4,%5,%6,%7}, {%8,%9}, {%0,%1,%2,%3};"
        : "+f"(c[0]), "+f"(c[1]), "+f"(c[2]), "+f"(c[3])
        : "r"(a[0]), "r"(a[1]), "r"(a[2]), "r"(a[3]), "r"(b[0]), "r"(b[1]));
}

extern __shared__ char dynsmem[];

__global__ __launch_bounds__(256) void gemm_unified(
    const __nv_bfloat16* __restrict__ A, const __nv_bfloat16* __restrict__ B,
    float* __restrict__ Cs, float* __restrict__ Cg)
{
    const int bj = blockIdx.x, bi = blockIdx.y;
    const uint32_t sb = smem_u32(dynsmem);
    const int tid  = threadIdx.x;
    const int wid  = tid >> 5, lane = tid & 31;
    const int wm   = (wid & 1) * 64;     // 2 warps in M
    const int wn   = (wid >> 1) * 32;    // 4 warps in N
    const int m0   = bi * BMT;
    const int n0   = bj * BN;

    auto load_stage = [&](int kt, int stg) {
        const uint32_t st = sb + stg * STAGE_BYTES;
        const size_t kofs = (size_t)kt * BKT;
#pragma unroll
        for (int q = 0; q < 8; q++) {
            int g = tid + q * 256;           // 0..2047
            int row = g >> 3, seg = g & 7;   // 256 rows x 8 segs(16B)
            const __nv_bfloat16* src = (row < BMT
                ? A + (size_t)(m0 + row) * KSPLIT
                : B + (size_t)(n0 + row - BMT) * KSPLIT) + kofs + seg * 8;
            cp16(st + row * ASTRIDE + seg * 16, src);
        }
    };

    float acc[4][4][4];
#pragma unroll
    for (int i = 0; i < 4; i++)
#pragma unroll
        for (int j = 0; j < 4; j++)
#pragma unroll
            for (int r = 0; r < 4; r++) acc[i][j][r] = 0.0f;

    load_stage(0, 0); CP_COMMIT();
    load_stage(1, 1); CP_COMMIT();

    const uint32_t aRowSel = (lane & 15);
    const uint32_t aKByte  = (lane >> 4) * 16;
    const uint32_t bRowSel = (lane & 7) + ((lane >> 4) << 3);
    const uint32_t bKByte  = ((lane >> 3) & 1) * 16;

    for (int kt = 0; kt < NKT; kt++) {
        CP_WAIT(1);
        __syncthreads();

        if (kt + 2 < NKT) load_stage(kt + 2, (kt + 2) % NSTG);
        CP_COMMIT();

        const uint32_t sa = sb + (kt % NSTG) * STAGE_BYTES;
        const uint32_t sB = sa + B_OFF;
#pragma unroll
        for (int ks = 0; ks < 4; ks++) {
            const uint32_t kb = ks * 32;     // 16 halves = 32B
            uint32_t a[4][4];
#pragma unroll
            for (int mf = 0; mf < 4; mf++) {
                uint32_t addr = sa + (wm + mf * 16 + aRowSel) * ASTRIDE + kb + aKByte;
                ldsm4(a[mf][0], a[mf][1], a[mf][2], a[mf][3], addr);
            }
            uint32_t b[4][2];
#pragma unroll
            for (int np = 0; np < 2; np++) {
                uint32_t addr = sB + (wn + np * 16 + bRowSel) * ASTRIDE + kb + bKByte;
                uint32_t r0, r1, r2, r3;
                ldsm4(r0, r1, r2, r3, addr);
                b[np * 2][0] = r0;     b[np * 2][1] = r1;
                b[np * 2 + 1][0] = r2; b[np * 2 + 1][1] = r3;
            }
#pragma unroll
            for (int mf = 0; mf < 4; mf++)
#pragma unroll
                for (int nf = 0; nf < 4; nf++)
                    mma16816(acc[mf][nf], a[mf], b[nf]);
        }
        __syncthreads();
    }

    // epilogue: route rows to scores (r<8192) or gram (r>=8192)
    const int erow = lane >> 2, ecol = (lane & 3) * 2;
#pragma unroll
    for (int mf = 0; mf < 4; mf++) {
#pragma unroll
        for (int nf = 0; nf < 4; nf++) {
            const int r = m0 + wm + mf * 16 + erow;
            const int c = n0 + wn + nf * 8 + ecol;
            float2 v0 = {acc[mf][nf][0], acc[mf][nf][1]};
            float2 v1 = {acc[mf][nf][2], acc[mf][nf][3]};
            float* dst0 = (r < BB)     ? Cs + (size_t)r * KK       : Cg + (size_t)(r - BB) * KK;
            float* dst1 = (r + 8 < BB) ? Cs + (size_t)(r + 8) * KK : Cg + (size_t)(r + 8 - BB) * KK;
            *(float2*)(dst0 + c) = v0;
            *(float2*)(dst1 + c) = v1;
        }
    }
}

// ---------------- initial ||target||^2 ----------------
__global__ __launch_bounds__(256) void norm0_kernel(const float* __restrict__ targets) {
    const int warp = threadIdx.x >> 5, lane = threadIdx.x & 31;
    const int row = blockIdx.x * 8 + warp;
    const float* tp = targets + (size_t)row * DD;
    float s = 0.0f;
#pragma unroll
    for (int c4 = lane; c4 < DD / 4; c4 += 32) {
        float4 v = *(const float4*)(tp + c4 * 4);
        s += v.x * v.x + v.y * v.y + v.z * v.z + v.w * v.w;
    }
#pragma unroll
    for (int off = 16; off; off >>= 1) s += __shfl_xor_sync(0xffffffffu, s, off);
    if (lane == 0) g_norm2[row] = s;
}

// ---------------- fused 8-step pursuit: block per row, score row in smem ----------------
__global__ __launch_bounds__(256) void step_fused(float* __restrict__ idx_out) {
    __shared__ float s[KK];
    __shared__ float rv[8];
    __shared__ int   ri[8];
    __shared__ int   gsel;

    const int tid = threadIdx.x;
    const int row = blockIdx.x;
    const int warp = tid >> 5, lane = tid & 31;

    const float4* sp = (const float4*)(g_scores + (size_t)row * KK);
#pragma unroll
    for (int i = 0; i < 4; i++) ((float4*)s)[tid + 256 * i] = sp[tid + 256 * i];

    float norm2 = 0.0f;
    bool active = true;
    if (tid == 0) norm2 = g_norm2[row];

    for (int step = 0; step < LL; step++) {
        __syncthreads();
        float bv = -3.402823466e38f; int bi = 0;
#pragma unroll
        for (int i = 0; i < 16; i++) {
            int c = tid + 256 * i;
            float v = s[c];
            if (v > bv || (v == bv && c < bi)) { bv = v; bi = c; }
        }
#pragma unroll
        for (int off = 16; off; off >>= 1) {
            float ov = __shfl_xor_sync(0xffffffffu, bv, off);
            int   oi = __shfl_xor_sync(0xffffffffu, bi, off);
            if (ov > bv || (ov == bv && oi < bi)) { bv = ov; bi = oi; }
        }
        if (lane == 0) { rv[warp] = bv; ri[warp] = bi; }
        __syncthreads();
        if (tid == 0) {
            bv = rv[0]; bi = ri[0];
#pragma unroll
            for (int w = 1; w < 8; w++)
                if (rv[w] > bv || (rv[w] == bv && ri[w] < bi)) { bv = rv[w]; bi = ri[w]; }
            const bool act = active && (norm2 >= 1e-6f);   // norm >= 1e-3
            active = act;
            idx_out[(size_t)row * LL + step] = act ? (float)bi : -1.0f;
            if (act) {
                const float d = c_decay[step];
                norm2 = norm2 - 2.0f * d * bv + d * d * g_gram[(size_t)bi * KK + bi];
            }
            gsel = act ? bi : -1;
        }
        __syncthreads();
        const int sel = gsel;
        if (sel >= 0 && step < LL - 1) {
            const float d = c_decay[step];
            const float4* gp = (const float4*)(g_gram + (size_t)sel * KK);
#pragma unroll
            for (int i = 0; i < 4; i++) {
                int c4 = tid + 256 * i;
                float4 g = gp[c4];
                float4 v = ((float4*)s)[c4];
                v.x -= d * g.x; v.y -= d * g.y; v.z -= d * g.z; v.w -= d * g.w;
                ((float4*)s)[c4] = v;
            }
        }
    }
}

// ---------------- final residual (reference subtraction order) ----------------
__global__ __launch_bounds__(256) void resid_kernel(
    const float* __restrict__ targets, const float* __restrict__ codebook,
    const float* __restrict__ idx_in, float* __restrict__ out)
{
    const int warp = threadIdx.x >> 5, lane = threadIdx.x & 31;
    const int row = blockIdx.x * 8 + warp;
    int sidx[LL];
#pragma unroll
    for (int s = 0; s < LL; s++) {
        float pv = idx_in[(size_t)row * LL + s];
        sidx[s] = (pv >= 0.0f) ? (int)pv : -1;
    }
    const float* tp = targets + (size_t)row * DD;
    float* op = out + (size_t)row * DD;
#pragma unroll
    for (int c4 = lane; c4 < DD / 4; c4 += 32) {
        float4 v = *(const float4*)(tp + c4 * 4);
#pragma unroll
        for (int s = 0; s < LL; s++) {
            if (sidx[s] >= 0) {
                const float d = c_decay[s];
                float4 c = *(const float4*)(codebook + (size_t)sidx[s] * DD + c4 * 4);
                v.x -= d * c.x; v.y -= d * c.y; v.z -= d * c.z; v.w -= d * c.w;
            }
        }
        *(float4*)(op + c4 * 4) = v;
    }
}

__global__ void f2i_kernel(const float* __restrict__ src, int* __restrict__ dst, int n) {
    int i = blockIdx.x * blockDim.x + threadIdx.x;
    if (i < n) dst[i] = (int)src[i];
}

// ---------------- host ----------------
extern "C" void kernel_launch(void* const* d_in, const int* in_sizes, int n_in,
                              void* d_out, int out_size)
{
    const float* targets  = (const float*)d_in[0];
    const float* codebook = (const float*)d_in[1];

    void *scoresPtr = nullptr, *gramPtr = nullptr, *scrPtr = nullptr;
    void *tcPtr = nullptr, *cbPtr = nullptr;
    cudaGetSymbolAddress(&scoresPtr, g_scores);
    cudaGetSymbolAddress(&gramPtr, g_gram);
    cudaGetSymbolAddress(&scrPtr, g_idx_scratch);
    cudaGetSymbolAddress(&tcPtr, g_TC);
    cudaGetSymbolAddress(&cbPtr, g_Cb);

    const int IDX_N = BB * LL, RES_N = BB * DD;
    float* out = (float*)d_out;
    const bool full_layout = (out_size >= IDX_N + RES_N);
    float* idx_out = full_layout ? out : (float*)scrPtr;
    float* res_out = full_layout ? (out + IDX_N)
                   : (out_size == RES_N ? out : (float*)scoresPtr);

    const int SMEM = NSTG * STAGE_BYTES;   // 110592
    static bool attr_done = false;
    if (!attr_done) {
        cudaFuncSetAttribute(gemm_unified, cudaFuncAttributeMaxDynamicSharedMemorySize, SMEM);
        attr_done = true;
    }

    // 1) bf16 3-way splits into unified A matrix + B-variant codebook
    split_targets<<<BB * DD / 256, 256>>>(targets);
    split_codebook<<<KK * DD / 256, 256>>>(codebook);

    // 2) one GEMM: [scores; gram] = [T;C]_A @ C_B^T
    gemm_unified<<<dim3(KK / BN, MTOT / BMT), 256, SMEM>>>(
        (const __nv_bfloat16*)tcPtr, (const __nv_bfloat16*)cbPtr,
        (float*)scoresPtr, (float*)gramPtr);

    // 3) norms, fused pursuit, residual
    norm0_kernel<<<BB / 8, 256>>>(targets);
    step_fused<<<BB, 256>>>(idx_out);
    resid_kernel<<<BB / 8, 256>>>(targets, codebook, idx_out, res_out);

    if (!full_layout && out_size == IDX_N) {
        f2i_kernel<<<(IDX_N + 255) / 256, 256>>>((const float*)scrPtr, (int*)d_out, IDX_N);
    }
}

// round 8
// speedup vs baseline: 1.0092x; 1.0092x over previous
#include <cuda_runtime.h>
#include <cuda_bf16.h>
#include <cstdint>
#include <math.h>

#define BB 8192   // batch
#define DD 1024   // dim
#define KK 4096   // codebook size
#define LL 8      // max word length
#define SLOT3 3072   // 3 bf16 planes (hi, mid, lo) per matrix row

// ---------------- persistent scratch ----------------
__device__ float         g_scores[BB * KK];          // 134 MB
__device__ float         g_gram[KK * KK];            //  67 MB
__device__ float         g_norm2[BB];
__device__ float         g_idx_scratch[BB * LL];
__device__ __nv_bfloat16 g_Ts[(size_t)BB * SLOT3];   // targets hi/mid/lo (50 MB)
__device__ __nv_bfloat16 g_Cs[(size_t)KK * SLOT3];   // codebook hi/mid/lo (25 MB)

__constant__ float c_decay[LL] = {
    1.0f, 0.9f, 0.81f, 0.729f, 0.6561f, 0.59049f, 0.531441f, 0.4782969f
};
// pairing slot schedule: pairings hh, mh, lh, hm, hl, mm (drops ml, lm, ll ~2^-27)
__constant__ int c_sa[6] = {0, 1, 2, 0, 0, 1};
__constant__ int c_sb[6] = {0, 0, 0, 1, 2, 1};

// ---------------- split conversion: fp32 -> {hi, mid, lo} bf16 planes ----------------
__global__ __launch_bounds__(256) void split3(const float* __restrict__ src,
                                              __nv_bfloat16* __restrict__ dst) {
    int i = blockIdx.x * 256 + threadIdx.x;             // over rows*DD
    float a = src[i];
    __nv_bfloat16 hi = __float2bfloat16(a);
    float r1 = a - __bfloat162float(hi);
    __nv_bfloat16 mid = __float2bfloat16(r1);
    __nv_bfloat16 lo  = __float2bfloat16(r1 - __bfloat162float(mid));
    size_t base = (size_t)(i >> 10) * SLOT3 + (i & 1023);
    dst[base] = hi;  dst[base + 1024] = mid;  dst[base + 2048] = lo;
}

// ---------------- mma.sync bf16 split GEMM ----------------
// C[m,n] = sum over 6 pairings of A_slot(sa) row m . B_slot(sb) row n
// Block 128x128, BKT=32, 3 stages, 8 warps (2M x 4N), 2 CTAs/SM.
#define BMT 128
#define BN 128
#define BKT 32
#define NSTG 3
#define NKT 192                  // 6 pairings * 1024 / 32
#define ASTRIDE 80               // 64B data + 16B pad per smem row
#define B_OFF (BMT * ASTRIDE)    // 10240
#define STAGE_BYTES ((BMT + BN) * ASTRIDE)   // 20480

__device__ __forceinline__ uint32_t smem_u32(const void* p) {
    uint32_t a;
    asm("{ .reg .u64 t; cvta.to.shared.u64 t, %1; cvt.u32.u64 %0, t; }" : "=r"(a) : "l"(p));
    return a;
}
__device__ __forceinline__ void cp16(uint32_t dst, const void* src) {
    asm volatile("cp.async.cg.shared.global [%0], [%1], 16;" :: "r"(dst), "l"(src) : "memory");
}
#define CP_COMMIT() asm volatile("cp.async.commit_group;" ::: "memory")
#define CP_WAIT(n)  asm volatile("cp.async.wait_group %0;" :: "n"(n) : "memory")

__device__ __forceinline__ void ldsm4(uint32_t& r0, uint32_t& r1, uint32_t& r2, uint32_t& r3,
                                      uint32_t addr) {
    asm volatile("ldmatrix.sync.aligned.m8n8.x4.shared.b16 {%0,%1,%2,%3}, [%4];"
                 : "=r"(r0), "=r"(r1), "=r"(r2), "=r"(r3) : "r"(addr));
}
__device__ __forceinline__ void mma16816(float* c, const uint32_t* a, const uint32_t* b) {
    asm volatile(
        "mma.sync.aligned.m16n8k16.row.col.f32.bf16.bf16.f32 "
        "{%0,%1,%2,%3}, {%4,%5,%6,%7}, {%8,%9}, {%0,%1,%2,%3};"
        : "+f"(c[0]), "+f"(c[1]), "+f"(c[2]), "+f"(c[3])
        : "r"(a[0]), "r"(a[1]), "r"(a[2]), "r"(a[3]), "r"(b[0]), "r"(b[1]));
}

extern __shared__ char dynsmem[];

__global__ __launch_bounds__(256, 2) void gemm_split3(
    const __nv_bfloat16* __restrict__ A, const __nv_bfloat16* __restrict__ B,
    float* __restrict__ C, int sym)
{
    int m0, n0, ti = 0, tj = 0;
    if (sym) {
        // triangular decode: b -> (i <= j), b = j(j+1)/2 + i
        int b = blockIdx.x;
        int j = (int)((sqrtf(8.0f * b + 1.0f) - 1.0f) * 0.5f);
        while ((j + 1) * (j + 2) / 2 <= b) j++;
        while (j * (j + 1) / 2 > b) j--;
        int i = b - j * (j + 1) / 2;
        ti = i; tj = j;
        m0 = i * BMT; n0 = j * BN;
    } else {
        m0 = blockIdx.y * BMT; n0 = blockIdx.x * BN;
    }

    const uint32_t sb = smem_u32(dynsmem);
    const int tid  = threadIdx.x;
    const int wid  = tid >> 5, lane = tid & 31;
    const int wm   = (wid & 1) * 64;     // 2 warps in M
    const int wn   = (wid >> 1) * 32;    // 4 warps in N

    auto load_stage = [&](int kt, int stg) {
        const uint32_t st = sb + stg * STAGE_BYTES;
        const int p = kt >> 5;                     // pairing 0..5
        const int krem = (kt & 31) * BKT;          // 0..992
        const int aoff = c_sa[p] * 1024 + krem;
        const int boff = c_sb[p] * 1024 + krem;
#pragma unroll
        for (int q = 0; q < 4; q++) {
            int g = tid + q * 256;                 // 0..1023
            int row = g >> 2, seg = g & 3;         // 256 rows x 4 segs(16B)
            const __nv_bfloat16* src = (row < BMT
                ? A + (size_t)(m0 + row) * SLOT3 + aoff
                : B + (size_t)(n0 + row - BMT) * SLOT3 + boff) + seg * 8;
            cp16(st + row * ASTRIDE + seg * 16, src);
        }
    };

    float acc[4][4][4];
#pragma unroll
    for (int i = 0; i < 4; i++)
#pragma unroll
        for (int j = 0; j < 4; j++)
#pragma unroll
            for (int r = 0; r < 4; r++) acc[i][j][r] = 0.0f;

    load_stage(0, 0); CP_COMMIT();
    load_stage(1, 1); CP_COMMIT();

    const uint32_t aRowSel = (lane & 15);
    const uint32_t aKByte  = (lane >> 4) * 16;
    const uint32_t bRowSel = (lane & 7) + ((lane >> 4) << 3);
    const uint32_t bKByte  = ((lane >> 3) & 1) * 16;

    for (int kt = 0; kt < NKT; kt++) {
        CP_WAIT(1);
        __syncthreads();

        if (kt + 2 < NKT) load_stage(kt + 2, (kt + 2) % NSTG);
        CP_COMMIT();

        const uint32_t sa = sb + (kt % NSTG) * STAGE_BYTES;
        const uint32_t sB = sa + B_OFF;
#pragma unroll
        for (int ks = 0; ks < 2; ks++) {
            const uint32_t kb = ks * 32;           // 16 halves = 32B
            uint32_t a[4][4];
#pragma unroll
            for (int mf = 0; mf < 4; mf++) {
                uint32_t addr = sa + (wm + mf * 16 + aRowSel) * ASTRIDE + kb + aKByte;
                ldsm4(a[mf][0], a[mf][1], a[mf][2], a[mf][3], addr);
            }
            uint32_t b[4][2];
#pragma unroll
            for (int np = 0; np < 2; np++) {
                uint32_t addr = sB + (wn + np * 16 + bRowSel) * ASTRIDE + kb + bKByte;
                uint32_t r0, r1, r2, r3;
                ldsm4(r0, r1, r2, r3, addr);
                b[np * 2][0] = r0;     b[np * 2][1] = r1;
                b[np * 2 + 1][0] = r2; b[np * 2 + 1][1] = r3;
            }
#pragma unroll
            for (int mf = 0; mf < 4; mf++)
#pragma unroll
                for (int nf = 0; nf < 4; nf++)
                    mma16816(acc[mf][nf], a[mf], b[nf]);
        }
        __syncthreads();
    }

    // normal (row-major) writes
    const int erow = lane >> 2, ecol = (lane & 3) * 2;
#pragma unroll
    for (int mf = 0; mf < 4; mf++) {
#pragma unroll
        for (int nf = 0; nf < 4; nf++) {
            const int r = m0 + wm + mf * 16 + erow;
            const int c = n0 + wn + nf * 8 + ecol;
            *(float2*)&C[(size_t)r * KK + c] =
                make_float2(acc[mf][nf][0], acc[mf][nf][1]);
            *(float2*)&C[(size_t)(r + 8) * KK + c] =
                make_float2(acc[mf][nf][2], acc[mf][nf][3]);
        }
    }

    // mirror tile via smem-staged coalesced transpose (off-diagonal sym blocks)
    if (sym && ti != tj) {
        float* ts = (float*)dynsmem;               // reuse pipeline smem: 64x128 f32
#pragma unroll
        for (int h = 0; h < 2; h++) {
            __syncthreads();
            if ((wn >> 6) == h) {                  // warps whose cols fall in this half
#pragma unroll
                for (int mf = 0; mf < 4; mf++)
#pragma unroll
                    for (int nf = 0; nf < 4; nf++) {
                        const int r = wm + mf * 16 + erow;
                        const int c = (wn & 63) + nf * 8 + ecol;
                        ts[c * 128 + r]            = acc[mf][nf][0];
                        ts[(c + 1) * 128 + r]      = acc[mf][nf][1];
                        ts[c * 128 + r + 8]        = acc[mf][nf][2];
                        ts[(c + 1) * 128 + r + 8]  = acc[mf][nf][3];
                    }
            }
            __syncthreads();
#pragma unroll
            for (int q = 0; q < 8; q++) {
                int g = tid + q * 256;             // 0..2047 float4 slots
                int row = g >> 5, c4 = g & 31;
                *(float4*)&C[(size_t)(n0 + h * 64 + row) * KK + m0 + c4 * 4] =
                    *(float4*)&ts[row * 128 + c4 * 4];
            }
        }
    }
}

// ---------------- initial ||target||^2 ----------------
__global__ __launch_bounds__(256) void norm0_kernel(const float* __restrict__ targets) {
    const int warp = threadIdx.x >> 5, lane = threadIdx.x & 31;
    const int row = blockIdx.x * 8 + warp;
    const float* tp = targets + (size_t)row * DD;
    float s = 0.0f;
#pragma unroll
    for (int c4 = lane; c4 < DD / 4; c4 += 32) {
        float4 v = *(const float4*)(tp + c4 * 4);
        s += v.x * v.x + v.y * v.y + v.z * v.z + v.w * v.w;
    }
#pragma unroll
    for (int off = 16; off; off >>= 1) s += __shfl_xor_sync(0xffffffffu, s, off);
    if (lane == 0) g_norm2[row] = s;
}

// ---------------- fused 8-step pursuit: block per row, score row in smem ----------------
__global__ __launch_bounds__(256) void step_fused(float* __restrict__ idx_out) {
    __shared__ float s[KK];
    __shared__ float rv[8];
    __shared__ int   ri[8];
    __shared__ int   gsel;

    const int tid = threadIdx.x;
    const int row = blockIdx.x;
    const int warp = tid >> 5, lane = tid & 31;

    const float4* sp = (const float4*)(g_scores + (size_t)row * KK);
#pragma unroll
    for (int i = 0; i < 4; i++) ((float4*)s)[tid + 256 * i] = sp[tid + 256 * i];

    float norm2 = 0.0f;
    bool active = true;
    if (tid == 0) norm2 = g_norm2[row];

    for (int step = 0; step < LL; step++) {
        __syncthreads();
        float bv = -3.402823466e38f; int bi = 0;
#pragma unroll
        for (int i = 0; i < 16; i++) {
            int c = tid + 256 * i;
            float v = s[c];
            if (v > bv || (v == bv && c < bi)) { bv = v; bi = c; }
        }
#pragma unroll
        for (int off = 16; off; off >>= 1) {
            float ov = __shfl_xor_sync(0xffffffffu, bv, off);
            int   oi = __shfl_xor_sync(0xffffffffu, bi, off);
            if (ov > bv || (ov == bv && oi < bi)) { bv = ov; bi = oi; }
        }
        if (lane == 0) { rv[warp] = bv; ri[warp] = bi; }
        __syncthreads();
        if (tid == 0) {
            bv = rv[0]; bi = ri[0];
#pragma unroll
            for (int w = 1; w < 8; w++)
                if (rv[w] > bv || (rv[w] == bv && ri[w] < bi)) { bv = rv[w]; bi = ri[w]; }
            const bool act = active && (norm2 >= 1e-6f);   // norm >= 1e-3
            active = act;
            idx_out[(size_t)row * LL + step] = act ? (float)bi : -1.0f;
            if (act) {
                const float d = c_decay[step];
                norm2 = norm2 - 2.0f * d * bv + d * d * g_gram[(size_t)bi * KK + bi];
            }
            gsel = act ? bi : -1;
        }
        __syncthreads();
        const int sel = gsel;
        if (sel >= 0 && step < LL - 1) {
            const float d = c_decay[step];
            const float4* gp = (const float4*)(g_gram + (size_t)sel * KK);
#pragma unroll
            for (int i = 0; i < 4; i++) {
                int c4 = tid + 256 * i;
                float4 g = gp[c4];
                float4 v = ((float4*)s)[c4];
                v.x -= d * g.x; v.y -= d * g.y; v.z -= d * g.z; v.w -= d * g.w;
                ((float4*)s)[c4] = v;
            }
        }
    }
}

// ---------------- final residual (reference subtraction order) ----------------
__global__ __launch_bounds__(256) void resid_kernel(
    const float* __restrict__ targets, const float* __restrict__ codebook,
    const float* __restrict__ idx_in, float* __restrict__ out)
{
    const int warp = threadIdx.x >> 5, lane = threadIdx.x & 31;
    const int row = blockIdx.x * 8 + warp;
    int sidx[LL];
#pragma unroll
    for (int s = 0; s < LL; s++) {
        float pv = idx_in[(size_t)row * LL + s];
        sidx[s] = (pv >= 0.0f) ? (int)pv : -1;
    }
    const float* tp = targets + (size_t)row * DD;
    float* op = out + (size_t)row * DD;
#pragma unroll
    for (int c4 = lane; c4 < DD / 4; c4 += 32) {
        float4 v = *(const float4*)(tp + c4 * 4);
#pragma unroll
        for (int s = 0; s < LL; s++) {
            if (sidx[s] >= 0) {
                const float d = c_decay[s];
                float4 c = *(const float4*)(codebook + (size_t)sidx[s] * DD + c4 * 4);
                v.x -= d * c.x; v.y -= d * c.y; v.z -= d * c.z; v.w -= d * c.w;
            }
        }
        *(float4*)(op + c4 * 4) = v;
    }
}

__global__ void f2i_kernel(const float* __restrict__ src, int* __restrict__ dst, int n) {
    int i = blockIdx.x * blockDim.x + threadIdx.x;
    if (i < n) dst[i] = (int)src[i];
}

// ---------------- host ----------------
extern "C" void kernel_launch(void* const* d_in, const int* in_sizes, int n_in,
                              void* d_out, int out_size)
{
    const float* targets  = (const float*)d_in[0];
    const float* codebook = (const float*)d_in[1];

    void *scoresPtr = nullptr, *gramPtr = nullptr, *scrPtr = nullptr;
    void *tsPtr = nullptr, *csPtr = nullptr;
    cudaGetSymbolAddress(&scoresPtr, g_scores);
    cudaGetSymbolAddress(&gramPtr, g_gram);
    cudaGetSymbolAddress(&scrPtr, g_idx_scratch);
    cudaGetSymbolAddress(&tsPtr, g_Ts);
    cudaGetSymbolAddress(&csPtr, g_Cs);

    const int IDX_N = BB * LL, RES_N = BB * DD;
    float* out = (float*)d_out;
    const bool full_layout = (out_size >= IDX_N + RES_N);
    float* idx_out = full_layout ? out : (float*)scrPtr;
    float* res_out = full_layout ? (out + IDX_N)
                   : (out_size == RES_N ? out : (float*)scoresPtr);

    const int SMEM = NSTG * STAGE_BYTES;   // 61440
    static bool attr_done = false;
    if (!attr_done) {
        cudaFuncSetAttribute(gemm_split3, cudaFuncAttributeMaxDynamicSharedMemorySize, SMEM);
        attr_done = true;
    }

    // 1) hi/mid/lo splits (3 planes each; pairing indexing happens in the GEMM loader)
    split3<<<BB * DD / 256, 256>>>(targets, (__nv_bfloat16*)tsPtr);
    split3<<<KK * DD / 256, 256>>>(codebook, (__nv_bfloat16*)csPtr);

    // 2) scores0 = T @ C^T (full grid) and G = C @ C^T (triangular grid + mirror)
    gemm_split3<<<dim3(KK / BN, BB / BMT), 256, SMEM>>>(
        (const __nv_bfloat16*)tsPtr, (const __nv_bfloat16*)csPtr, (float*)scoresPtr, 0);
    gemm_split3<<<(KK / BMT) * (KK / BMT + 1) / 2, 256, SMEM>>>(
        (const __nv_bfloat16*)csPtr, (const __nv_bfloat16*)csPtr, (float*)gramPtr, 1);

    // 3) norms, fused pursuit, residual
    norm0_kernel<<<BB / 8, 256>>>(targets);
    step_fused<<<BB, 256>>>(idx_out);
    resid_kernel<<<BB / 8, 256>>>(targets, codebook, idx_out, res_out);

    if (!full_layout && out_size == IDX_N) {
        f2i_kernel<<<(IDX_N + 255) / 256, 256>>>((const float*)scrPtr, (int*)d_out, IDX_N);
    }
}